// round 2
// baseline (speedup 1.0000x reference)
#include <cuda_runtime.h>
#include <cuda_bf16.h>

// Problem constants (fixed shapes)
#define BB 4
#define NN 16384
#define DD 128
#define PP 100
#define BN (BB * NN)        // 65536
#define NSEG (PP * BB)      // 400

// Scratch (device globals: allocation-free rule)
__device__ float g_xproj[NSEG * NN];   // later overwritten with diff
__device__ float g_yproj[NSEG * NN];
__device__ float g_theta[PP * DD];     // normalized thetas

// ---------------------------------------------------------------------------
// Kernel 1: normalize theta rows (norm over D, eps clamp 1e-12)
// ---------------------------------------------------------------------------
__global__ void norm_kernel(const float* __restrict__ thetas) {
    int p = blockIdx.x;
    int d = threadIdx.x;          // 128 threads
    float v = thetas[p * DD + d];
    float s = v * v;
    #pragma unroll
    for (int o = 16; o; o >>= 1) s += __shfl_xor_sync(0xFFFFFFFFu, s, o);
    __shared__ float ws[4];
    if ((d & 31) == 0) ws[d >> 5] = s;
    __syncthreads();
    float tot = ws[0] + ws[1] + ws[2] + ws[3];
    float nrm = fmaxf(sqrtf(tot), 1e-12f);
    g_theta[p * DD + d] = v / nrm;
}

// ---------------------------------------------------------------------------
// Kernel 2: projections. Block handles R=16 consecutive rows (bn) for BOTH
// x and y. Thread p (p < 100) computes dot(row_r, theta_p) for all 16 rows.
// Output layout: proj[(p*B + b)*N + n] so each sort segment is contiguous.
// ---------------------------------------------------------------------------
#define PROJ_R 16
__global__ void __launch_bounds__(128) proj_kernel(
    const float* __restrict__ x, const float* __restrict__ y)
{
    extern __shared__ float sm[];
    float* th_s = sm;                    // P*D = 12800 floats
    float* x_s  = th_s + PP * DD;        // R*D = 2048
    float* y_s  = x_s + PROJ_R * DD;     // R*D = 2048

    int tid  = threadIdx.x;
    int row0 = blockIdx.x * PROJ_R;      // global bn of first row

    // load normalized thetas
    for (int i = tid; i < PP * DD; i += 128) th_s[i] = g_theta[i];

    // load x/y tiles (vectorized)
    const float4* xv = (const float4*)(x + (size_t)row0 * DD);
    const float4* yv = (const float4*)(y + (size_t)row0 * DD);
    float4* xs4 = (float4*)x_s;
    float4* ys4 = (float4*)y_s;
    const int NV = PROJ_R * DD / 4;      // 512
    for (int i = tid; i < NV; i += 128) { xs4[i] = xv[i]; ys4[i] = yv[i]; }
    __syncthreads();

    int p = tid;
    if (p < PP) {
        float ax[PROJ_R], ay[PROJ_R];
        #pragma unroll
        for (int r = 0; r < PROJ_R; ++r) { ax[r] = 0.f; ay[r] = 0.f; }
        const float* thp = th_s + p * DD;
        for (int d = 0; d < DD; ++d) {
            float th = thp[d];
            #pragma unroll
            for (int r = 0; r < PROJ_R; ++r) {
                ax[r] = fmaf(x_s[r * DD + d], th, ax[r]);
                ay[r] = fmaf(y_s[r * DD + d], th, ay[r]);
            }
        }
        int b  = row0 >> 14;             // row0 / N
        int n0 = row0 & (NN - 1);
        size_t base = (size_t)(p * BB + b) * NN + n0;
        float4* ox = (float4*)(g_xproj + base);
        float4* oy = (float4*)(g_yproj + base);
        #pragma unroll
        for (int q = 0; q < PROJ_R / 4; ++q) {
            ox[q] = make_float4(ax[4*q], ax[4*q+1], ax[4*q+2], ax[4*q+3]);
            oy[q] = make_float4(ay[4*q], ay[4*q+1], ay[4*q+2], ay[4*q+3]);
        }
    }
}

// ---------------------------------------------------------------------------
// Kernel 3: per-segment bitonic sort (16384 elems) of y values and of
// (x value, index) pairs, then write diff[n] = y_sorted[i] - x_sorted[i]
// at n = x_argsort[i], in place into g_xproj.
// smem: 64KB ykey + 64KB xkey + 32KB uint16 idx = 160KB  -> 1 CTA/SM
// ---------------------------------------------------------------------------
__global__ void __launch_bounds__(1024) sort_kernel() {
    extern __shared__ unsigned char smraw[];
    float* ykey = (float*)smraw;
    float* xkey = ykey + NN;
    unsigned short* xidx = (unsigned short*)(xkey + NN);

    const int tid = threadIdx.x;
    const size_t base = (size_t)blockIdx.x * NN;

    for (int i = tid; i < NN; i += 1024) {
        ykey[i] = g_yproj[base + i];
        xkey[i] = g_xproj[base + i];
        xidx[i] = (unsigned short)i;
    }
    __syncthreads();

    for (int k = 2; k <= NN; k <<= 1) {
        for (int j = k >> 1; j > 0; j >>= 1) {
            #pragma unroll 2
            for (int t = tid; t < NN / 2; t += 1024) {
                unsigned i = ((t & ~(j - 1)) << 1) | (t & (j - 1));
                unsigned l = i | j;
                bool dir = (i & k) == 0;   // ascending half
                // y (keys only)
                float a = ykey[i], c = ykey[l];
                if ((a > c) == dir) { ykey[i] = c; ykey[l] = a; }
                // x (keys + payload)
                float e = xkey[i], f = xkey[l];
                if ((e > f) == dir) {
                    xkey[i] = f; xkey[l] = e;
                    unsigned short ti = xidx[i]; xidx[i] = xidx[l]; xidx[l] = ti;
                }
            }
            __syncthreads();
        }
    }

    // diff[n] = y_sorted[i] - x_sorted[i], n = argsort_x[i]  (overwrite xproj)
    for (int i = tid; i < NN; i += 1024) {
        g_xproj[base + xidx[i]] = ykey[i] - xkey[i];
    }
}

// ---------------------------------------------------------------------------
// Kernel 4: out[bn, d] = x[bn, d] + (1/P) * sum_p diff[p, bn] * theta[p, d]
// Block: 128 threads (one per d), tile of OUT_R=64 rows.
// ---------------------------------------------------------------------------
#define OUT_R 64
__global__ void __launch_bounds__(128) out_kernel(
    const float* __restrict__ x, float* __restrict__ out)
{
    extern __shared__ float sm[];
    float* th_s   = sm;                  // P*D = 12800 floats (51.2KB)
    float* diff_s = th_s + PP * DD;      // P*OUT_R = 6400 floats (25.6KB)

    int tid  = threadIdx.x;
    int row0 = blockIdx.x * OUT_R;
    int b    = row0 >> 14;
    int n0   = row0 & (NN - 1);

    for (int i = tid; i < PP * DD; i += 128) th_s[i] = g_theta[i];

    // diff_s[p*OUT_R + r] = g_xproj[(p*B+b)*N + n0 + r]
    for (int i = tid; i < PP * OUT_R; i += 128) {
        int p = i / OUT_R;
        int r = i - p * OUT_R;
        diff_s[i] = g_xproj[(size_t)(p * BB + b) * NN + n0 + r];
    }
    __syncthreads();

    int d = tid;
    float acc[OUT_R];
    #pragma unroll
    for (int r = 0; r < OUT_R; ++r) acc[r] = 0.f;

    for (int p = 0; p < PP; ++p) {
        float th = th_s[p * DD + d];
        const float* dp = diff_s + p * OUT_R;
        #pragma unroll
        for (int r = 0; r < OUT_R; ++r) acc[r] = fmaf(dp[r], th, acc[r]);
    }

    const float scale = 1.0f / (float)PP;
    #pragma unroll 8
    for (int r = 0; r < OUT_R; ++r) {
        size_t idx = (size_t)(row0 + r) * DD + d;
        out[idx] = x[idx] + acc[r] * scale;
    }
}

// ---------------------------------------------------------------------------
extern "C" void kernel_launch(void* const* d_in, const int* in_sizes, int n_in,
                              void* d_out, int out_size) {
    const float* x      = (const float*)d_in[0];
    const float* y      = (const float*)d_in[1];
    const float* thetas = (const float*)d_in[2];
    float* out          = (float*)d_out;

    const int smem_proj = (PP * DD + 2 * PROJ_R * DD) * sizeof(float);   // 67584
    const int smem_sort = NN * sizeof(float) * 2 + NN * sizeof(unsigned short); // 163840
    const int smem_out  = (PP * DD + PP * OUT_R) * sizeof(float);        // 76800

    cudaFuncSetAttribute(proj_kernel, cudaFuncAttributeMaxDynamicSharedMemorySize, smem_proj);
    cudaFuncSetAttribute(sort_kernel, cudaFuncAttributeMaxDynamicSharedMemorySize, smem_sort);
    cudaFuncSetAttribute(out_kernel,  cudaFuncAttributeMaxDynamicSharedMemorySize, smem_out);

    norm_kernel<<<PP, DD>>>(thetas);
    proj_kernel<<<BN / PROJ_R, 128, smem_proj>>>(x, y);
    sort_kernel<<<NSEG, 1024, smem_sort>>>();
    out_kernel<<<BN / OUT_R, 128, smem_out>>>(x, out);
}

// round 3
// speedup vs baseline: 1.5376x; 1.5376x over previous
#include <cuda_runtime.h>
#include <cuda_bf16.h>

// Problem constants (fixed shapes)
#define BB 4
#define NN 16384
#define DD 128
#define PP 100
#define BN (BB * NN)        // 65536
#define NSEG (PP * BB)      // 400

// Scratch (device globals: allocation-free rule)
__device__ __align__(16) float g_xproj[NSEG * NN];   // later overwritten with diff
__device__ __align__(16) float g_yproj[NSEG * NN];
__device__ __align__(16) float g_theta[PP * DD];     // normalized thetas

// ---------------------------------------------------------------------------
// helpers
// ---------------------------------------------------------------------------
__device__ __forceinline__ unsigned f2o(float f) {
    unsigned u = __float_as_uint(f);
    return u ^ ((unsigned)((int)u >> 31) | 0x80000000u);
}
__device__ __forceinline__ float o2f(unsigned o) {
    unsigned mask = (~(unsigned)((int)o >> 31)) | 0x80000000u;
    return __uint_as_float(o ^ mask);
}
__device__ __forceinline__ void fma2(unsigned long long& d,
                                     unsigned long long a,
                                     unsigned long long b) {
    asm("fma.rn.f32x2 %0, %1, %2, %3;" : "=l"(d) : "l"(a), "l"(b), "l"(d));
}
__device__ __forceinline__ unsigned long long packf2(float lo, float hi) {
    unsigned long long r;
    asm("mov.b64 %0, {%1, %2};" : "=l"(r) : "f"(lo), "f"(hi));
    return r;
}
__device__ __forceinline__ float2 unpackf2(unsigned long long v) {
    float lo, hi;
    asm("mov.b64 {%0, %1}, %2;" : "=f"(lo), "=f"(hi) : "l"(v));
    return make_float2(lo, hi);
}

// ---------------------------------------------------------------------------
// Kernel 1: normalize theta rows (norm over D, eps clamp 1e-12)
// ---------------------------------------------------------------------------
__global__ void norm_kernel(const float* __restrict__ thetas) {
    int p = blockIdx.x;
    int d = threadIdx.x;          // 128 threads
    float v = thetas[p * DD + d];
    float s = v * v;
    #pragma unroll
    for (int o = 16; o; o >>= 1) s += __shfl_xor_sync(0xFFFFFFFFu, s, o);
    __shared__ float ws[4];
    if ((d & 31) == 0) ws[d >> 5] = s;
    __syncthreads();
    float tot = ws[0] + ws[1] + ws[2] + ws[3];
    float nrm = fmaxf(sqrtf(tot), 1e-12f);
    g_theta[p * DD + d] = v / nrm;
}

// ---------------------------------------------------------------------------
// Kernel 2: projections with packed f32x2 FMAs.
// Block handles R=16 rows for BOTH x and y; thread p computes all 16 dots.
// Output layout: proj[(p*B + b)*N + n] so each sort segment is contiguous.
// ---------------------------------------------------------------------------
#define PROJ_R 16
__global__ void __launch_bounds__(128) proj_kernel(
    const float* __restrict__ x, const float* __restrict__ y)
{
    extern __shared__ float sm[];
    float* th_s = sm;                    // P*D = 12800 floats
    float* x_s  = th_s + PP * DD;        // R*D = 2048
    float* y_s  = x_s + PROJ_R * DD;     // R*D = 2048

    int tid  = threadIdx.x;
    int row0 = blockIdx.x * PROJ_R;      // global bn of first row

    for (int i = tid; i < PP * DD; i += 128) th_s[i] = g_theta[i];

    const float4* xv4 = (const float4*)(x + (size_t)row0 * DD);
    const float4* yv4 = (const float4*)(y + (size_t)row0 * DD);
    float4* xs4 = (float4*)x_s;
    float4* ys4 = (float4*)y_s;
    const int NV = PROJ_R * DD / 4;      // 512
    for (int i = tid; i < NV; i += 128) { xs4[i] = xv4[i]; ys4[i] = yv4[i]; }
    __syncthreads();

    int p = tid;
    if (p < PP) {
        unsigned long long ax2[PROJ_R], ay2[PROJ_R];
        #pragma unroll
        for (int r = 0; r < PROJ_R; ++r) { ax2[r] = 0ull; ay2[r] = 0ull; }
        const float* thp = th_s + p * DD;
        for (int dd = 0; dd < DD; dd += 4) {
            ulonglong2 th2 = *(const ulonglong2*)(thp + dd);
            #pragma unroll
            for (int r = 0; r < PROJ_R; ++r) {
                ulonglong2 xv = *(const ulonglong2*)(x_s + r * DD + dd);
                fma2(ax2[r], xv.x, th2.x);
                fma2(ax2[r], xv.y, th2.y);
                ulonglong2 yv = *(const ulonglong2*)(y_s + r * DD + dd);
                fma2(ay2[r], yv.x, th2.x);
                fma2(ay2[r], yv.y, th2.y);
            }
        }
        float ax[PROJ_R], ay[PROJ_R];
        #pragma unroll
        for (int r = 0; r < PROJ_R; ++r) {
            float2 a = unpackf2(ax2[r]); ax[r] = a.x + a.y;
            float2 b = unpackf2(ay2[r]); ay[r] = b.x + b.y;
        }
        int b  = row0 >> 14;             // row0 / N
        int n0 = row0 & (NN - 1);
        size_t base = (size_t)(p * BB + b) * NN + n0;
        float4* ox = (float4*)(g_xproj + base);
        float4* oy = (float4*)(g_yproj + base);
        #pragma unroll
        for (int q = 0; q < PROJ_R / 4; ++q) {
            ox[q] = make_float4(ax[4*q], ax[4*q+1], ax[4*q+2], ax[4*q+3]);
            oy[q] = make_float4(ay[4*q], ay[4*q+1], ay[4*q+2], ay[4*q+3]);
        }
    }
}

// ---------------------------------------------------------------------------
// Kernel 3: register-blocked bitonic sort, 1024 threads x 16 elems/thread.
//   j <= 8          : in-register compare-exchange (no sync)
//   16 <= j <= 256  : warp shfl_xor exchange (no sync)
//   j >= 512        : smem exchange, XOR-swizzled to avoid bank conflicts
// y sorted as u32 ordered keys; x sorted as u64 (key32<<32 | idx) -> exact
// argsort. diff[n] = y_sorted[i] - x_sorted[i] at n = idx[i], into g_xproj.
// smem: 64KB (u32 y buffer) + 128KB (u64 x buffer) = 192KB -> 1 CTA/SM.
// ---------------------------------------------------------------------------
template <typename K, int SWM>
__device__ __forceinline__ void bitonic16(K (&v)[16], K* __restrict__ buf, const int t) {
    #pragma unroll 1
    for (int k = 2; k <= NN; k <<= 1) {
        // --- smem exchange steps (j >= 512) ---
        #pragma unroll 1
        for (int j = k >> 1; j >= 512; j >>= 1) {
            #pragma unroll
            for (int e = 0; e < 16; ++e) {
                int a = t * 16 + e;
                buf[a ^ ((a >> 4) & SWM)] = v[e];
            }
            __syncthreads();
            int pd = j >> 4;
            int pt = t ^ pd;
            bool keepmin = (((t & pd) == 0) == (((t << 4) & k) == 0));
            #pragma unroll
            for (int e = 0; e < 16; ++e) {
                int a = pt * 16 + e;
                K pv = buf[a ^ ((a >> 4) & SWM)];
                K mn = v[e] < pv ? v[e] : pv;
                K mx = v[e] < pv ? pv : v[e];
                v[e] = keepmin ? mn : mx;
            }
            __syncthreads();
        }
        // --- warp shuffle steps (16 <= j <= 256) ---
        {
            int j0 = ((k >> 1) < 256) ? (k >> 1) : 256;
            #pragma unroll 1
            for (int j = j0; j >= 16; j >>= 1) {
                int ld = j >> 4;
                bool keepmin = (((t & ld) == 0) == (((t << 4) & k) == 0));
                #pragma unroll
                for (int e = 0; e < 16; ++e) {
                    K pv = __shfl_xor_sync(0xFFFFFFFFu, v[e], ld);
                    K mn = v[e] < pv ? v[e] : pv;
                    K mx = v[e] < pv ? pv : v[e];
                    v[e] = keepmin ? mn : mx;
                }
            }
        }
        // --- in-register steps (j <= 8) ---
        #pragma unroll
        for (int jj = 8; jj >= 1; jj >>= 1) {
            if (jj < k) {
                #pragma unroll
                for (int e = 0; e < 16; ++e) {
                    if (!(e & jj)) {
                        bool asc = (((t * 16 + e) & k) == 0);
                        K a = v[e], b = v[e | jj];
                        K lo = a < b ? a : b;
                        K hi = a < b ? b : a;
                        v[e]      = asc ? lo : hi;
                        v[e | jj] = asc ? hi : lo;
                    }
                }
            }
        }
    }
}

__global__ void __launch_bounds__(1024, 1) sort_kernel() {
    extern __shared__ unsigned char smraw[];
    unsigned* bufY = (unsigned*)smraw;                                   // NN u32
    unsigned long long* bufX = (unsigned long long*)(smraw + NN * 4);    // NN u64

    const int t = threadIdx.x;
    const size_t base = (size_t)blockIdx.x * NN;

    // ---- phase 1: sort y keys ----
    {
        unsigned vy[16];
        const uint4* src = (const uint4*)(g_yproj + base) + t * 4;
        #pragma unroll
        for (int q = 0; q < 4; ++q) {
            uint4 w = src[q];
            vy[4*q+0] = f2o(__uint_as_float(w.x));
            vy[4*q+1] = f2o(__uint_as_float(w.y));
            vy[4*q+2] = f2o(__uint_as_float(w.z));
            vy[4*q+3] = f2o(__uint_as_float(w.w));
        }
        bitonic16<unsigned, 31>(vy, bufY, t);
        #pragma unroll
        for (int e = 0; e < 16; ++e) {
            int a = t * 16 + e;
            bufY[a ^ ((a >> 4) & 31)] = vy[e];
        }
    }
    __syncthreads();

    // ---- phase 2: sort (x key, idx) as u64 ----
    unsigned long long vx[16];
    {
        const uint4* src = (const uint4*)(g_xproj + base) + t * 4;
        #pragma unroll
        for (int q = 0; q < 4; ++q) {
            uint4 w = src[q];
            int i0 = t * 16 + 4 * q;
            vx[4*q+0] = ((unsigned long long)f2o(__uint_as_float(w.x)) << 32) | (unsigned)(i0 + 0);
            vx[4*q+1] = ((unsigned long long)f2o(__uint_as_float(w.y)) << 32) | (unsigned)(i0 + 1);
            vx[4*q+2] = ((unsigned long long)f2o(__uint_as_float(w.z)) << 32) | (unsigned)(i0 + 2);
            vx[4*q+3] = ((unsigned long long)f2o(__uint_as_float(w.w)) << 32) | (unsigned)(i0 + 3);
        }
    }
    bitonic16<unsigned long long, 15>(vx, bufX, t);

    // ---- phase 3: diff[n] = y_sorted[i] - x_sorted[i] at n = idx[i] ----
    #pragma unroll
    for (int e = 0; e < 16; ++e) {
        int i = t * 16 + e;
        float yv = o2f(bufY[i ^ ((i >> 4) & 31)]);
        unsigned long long kx = vx[e];
        unsigned idx = (unsigned)kx & 0xFFFFu;
        float xv = o2f((unsigned)(kx >> 32));
        g_xproj[base + idx] = yv - xv;
    }
}

// ---------------------------------------------------------------------------
// Kernel 4: out[bn, d] = x[bn, d] + (1/P) * sum_p diff[p, bn] * theta[p, d]
// Packed f32x2 FMAs; diff pairs loaded as ulonglong2 (native f32x2 operands).
// ---------------------------------------------------------------------------
#define OUT_R 64
__global__ void __launch_bounds__(128) out_kernel(
    const float* __restrict__ x, float* __restrict__ out)
{
    extern __shared__ float sm[];
    float* th_s   = sm;                  // P*D = 12800 floats (51.2KB)
    float* diff_s = th_s + PP * DD;      // P*OUT_R = 6400 floats (25.6KB)

    int tid  = threadIdx.x;
    int row0 = blockIdx.x * OUT_R;
    int b    = row0 >> 14;
    int n0   = row0 & (NN - 1);

    for (int i = tid; i < PP * DD; i += 128) th_s[i] = g_theta[i];

    // diff_s[p*OUT_R + r] = g_xproj[(p*B+b)*N + n0 + r]
    for (int i = tid; i < PP * OUT_R; i += 128) {
        int p = i >> 6;
        int r = i & 63;
        diff_s[i] = g_xproj[(size_t)(p * BB + b) * NN + n0 + r];
    }
    __syncthreads();

    int d = tid;
    unsigned long long acc2[OUT_R / 2];      // acc2[m] holds rows (2m, 2m+1)
    #pragma unroll
    for (int m = 0; m < OUT_R / 2; ++m) acc2[m] = 0ull;

    for (int p = 0; p < PP; ++p) {
        float th = th_s[p * DD + d];
        unsigned long long th2 = packf2(th, th);
        const ulonglong2* dp = (const ulonglong2*)(diff_s + p * OUT_R);
        #pragma unroll
        for (int q = 0; q < OUT_R / 4; ++q) {
            ulonglong2 dv = dp[q];           // rows 4q..4q+3, pre-packed pairs
            fma2(acc2[2*q],   dv.x, th2);
            fma2(acc2[2*q+1], dv.y, th2);
        }
    }

    const float scale = 1.0f / (float)PP;
    #pragma unroll
    for (int m = 0; m < OUT_R / 2; ++m) {
        float2 a = unpackf2(acc2[m]);
        size_t i0 = (size_t)(row0 + 2*m) * DD + d;
        out[i0]      = x[i0]      + a.x * scale;
        out[i0 + DD] = x[i0 + DD] + a.y * scale;
    }
}

// ---------------------------------------------------------------------------
extern "C" void kernel_launch(void* const* d_in, const int* in_sizes, int n_in,
                              void* d_out, int out_size) {
    const float* x      = (const float*)d_in[0];
    const float* y      = (const float*)d_in[1];
    const float* thetas = (const float*)d_in[2];
    float* out          = (float*)d_out;

    const int smem_proj = (PP * DD + 2 * PROJ_R * DD) * sizeof(float);            // 67584
    const int smem_sort = NN * sizeof(unsigned) + NN * sizeof(unsigned long long); // 196608
    const int smem_out  = (PP * DD + PP * OUT_R) * sizeof(float);                  // 76800

    cudaFuncSetAttribute(proj_kernel, cudaFuncAttributeMaxDynamicSharedMemorySize, smem_proj);
    cudaFuncSetAttribute(sort_kernel, cudaFuncAttributeMaxDynamicSharedMemorySize, smem_sort);
    cudaFuncSetAttribute(out_kernel,  cudaFuncAttributeMaxDynamicSharedMemorySize, smem_out);

    norm_kernel<<<PP, DD>>>(thetas);
    proj_kernel<<<BN / PROJ_R, 128, smem_proj>>>(x, y);
    sort_kernel<<<NSEG, 1024, smem_sort>>>();
    out_kernel<<<BN / OUT_R, 128, smem_out>>>(x, out);
}